// round 11
// baseline (speedup 1.0000x reference)
#include <cuda_runtime.h>

// Kalman: NCV(4) + 128 static sensor biases, T=4096.
// Round 11: remove the serial ybar staging pipeline.
//  - Workers 0..63: obs tile -> ybar chunk (flag + ctrA), sensor chunk sums
//    (ctrB barrier), full-MLP prefix + replay partials (ctrC).
//  - Master block 64:
//      warp0: Riccati t<128 immediately; warp1: mean chain reading ybar
//      DIRECTLY from global (flag-gated per chunk, L1-resident after first
//      touch), lagging warp0 one 32-step window (named barrier 1).
//      After phase1: ctrA poll (free by then), bulk coalesced ybar stage,
//      Lagrange gain fill (tau=64/96/128), 124x32 affine scan, shuffle
//      reductions, output, sync-state reset.

#define T_STEPS 4096
#define OBS 128
#define T1 128
#define WIN1 32
#define NW1 (T1 / WIN1)               // 4
#define WIN2 32
#define CH2 ((T_STEPS - T1) / WIN2)   // 124
#define NCHK 64                        // worker chunks (64 steps each)

__device__ float g_ybar[2 * T_STEPS];
__device__ float g_csum[NCHK * OBS];
__device__ float g_accp[NCHK * OBS];
__device__ int   g_flagY[NCHK];
__device__ int   g_ctrA, g_ctrB, g_ctrC;

__device__ __forceinline__ float frcp(float x) {
    float r;
    asm("rcp.approx.f32 %0, %1;" : "=f"(r) : "f"(x));
    return r;
}
__device__ __forceinline__ int ldacq(const int* p) {
    int v;
    asm volatile("ld.acquire.gpu.s32 %0, [%1];" : "=r"(v) : "l"(p) : "memory");
    return v;
}
__device__ __forceinline__ void strel(int* p, int v) {
    asm volatile("st.release.gpu.s32 [%0], %1;" :: "l"(p), "r"(v) : "memory");
}

// ---- master smem layout (float offsets) ----
#define OFF_G    0            // float4[4096]  -> 16384
#define OFF_YB   16384        // float2[4096]  ->  8192
#define OFF_BND  24576        // (CH2+1)*6 = 750 -> 752
#define OFF_CMP  25328        // CH2*12 = 1488
#define OFF_RED  26816        // 32
#define OFF_FIT  26848        // 16
#define OFF_PUB  26864        // 16
#define SMEM_FLOATS 26880
#define SMEM_BYTES  (SMEM_FLOATS * 4)

// Lagrange nodes x = 1/tau at tau = 64, 96, 128
#define XA (1.0f / 64.0f)
#define XB (1.0f / 96.0f)
#define XC (1.0f / 128.0f)
#define IDA (  24576.0f)
#define IDB ( -73728.0f)
#define IDC (  49152.0f)

__global__ void __launch_bounds__(256, 1) fused_kernel(
    const float4* __restrict__ obs4,
    const float* __restrict__ lbs,
    const float* __restrict__ lon,
    const float* __restrict__ ltn,
    float* __restrict__ out)
{
    extern __shared__ float smem[];
    const int tid  = threadIdx.x;
    const int bid  = blockIdx.x;
    const int wid  = tid >> 5;
    const int lane = tid & 31;

    const float R  = expf(2.0f * lon[0]);
    const float q  = expf(2.0f * ltn[0]);
    const float g0 = expf(2.0f * lbs[0]);

    if (bid < NCHK) {
        // ==================== WORKER block: chunk bid ====================
        float* tile = smem;            // [64][128] floats (32 KB)
        float* yloc = smem + 8192;     // [2*64]
        float* itg  = smem + 8320;     // [64]
        float* iaT  = smem + 8384;     // [64]
        const int c  = bid;
        const int c0 = c * 64;

        // step 1: load tile + ybar for this chunk
        #pragma unroll
        for (int k = 0; k < 8; ++k) {
            int tl = wid * 8 + k;
            int t  = c0 + tl;
            float4 v = obs4[t * 32 + lane];
            ((float4*)tile)[tl * 32 + lane] = v;
            float s = (v.x + v.y) + (v.z + v.w);
            #pragma unroll
            for (int m = 8; m; m >>= 1)
                s += __shfl_xor_sync(0xffffffffu, s, m);
            s *= 0.015625f;
            if (lane == 0)  { yloc[2 * tl]     = s; g_ybar[2 * t]     = s; }
            if (lane == 16) { yloc[2 * tl + 1] = s; g_ybar[2 * t + 1] = s; }
        }
        if (tid < 64) {
            int t = c0 + tid;
            float den0 = fmaf((float)t, g0, R);
            float den1 = den0 + g0;
            itg[tid] = g0 * frcp(den0);
            iaT[tid] = den0 * frcp(den1) * frcp(R);
        }
        __syncthreads();
        if (tid == 0) {
            strel(&g_flagY[c], 1);             // publish ybar chunk
            __threadfence();
            atomicAdd(&g_ctrA, 1);
        }

        // step 2: per-sensor chunk sums
        if (tid < OBS) {
            const int comp = tid >> 6;
            float cs = 0.0f;
            #pragma unroll 8
            for (int i = 0; i < 64; ++i)
                cs += tile[i * OBS + tid] - yloc[2 * i + comp];
            g_csum[c * OBS + tid] = cs;
        }
        __syncthreads();
        if (tid == 0) {
            __threadfence();
            atomicAdd(&g_ctrB, 1);
            while (ldacq(&g_ctrB) < NCHK) {}
        }
        __syncthreads();

        // step 3: exclusive prefix (full-MLP, predicated) + replay partial
        if (tid < OBS) {
            const float* cp = g_csum + tid;
            float p0 = 0.f, p1 = 0.f, p2 = 0.f, p3 = 0.f;
            #pragma unroll
            for (int k = 0; k < NCHK; k += 4) {
                if (k     < c) p0 += cp[(k    ) * OBS];
                if (k + 1 < c) p1 += cp[(k + 1) * OBS];
                if (k + 2 < c) p2 += cp[(k + 2) * OBS];
                if (k + 3 < c) p3 += cp[(k + 3) * OBS];
            }
            float S = (p0 + p1) + (p2 + p3);
            const int comp = tid >> 6;
            float acc = 0.0f;
            #pragma unroll 8
            for (int i = 0; i < 64; ++i) {
                float x  = tile[i * OBS + tid] - yloc[2 * i + comp];
                float rt = fmaf(-S, itg[i], x);
                S += x;
                acc = fmaf(iaT[i], rt * rt, acc);
            }
            g_accp[c * OBS + tid] = acc;
        }
        __syncthreads();
        if (tid == 0) { __threadfence(); atomicAdd(&g_ctrC, 1); }
        return;
    }

    // ======================= MASTER block =======================
    float4* Gp    = (float4*)(smem + OFF_G);
    float2* ybp   = (float2*)(smem + OFF_YB);
    float*  s_bnd = smem + OFF_BND;
    float*  s_cmp = smem + OFF_CMP;
    float*  s_red = smem + OFF_RED;
    float*  s_fit = smem + OFF_FIT;
    float*  s_pub = smem + OFF_PUB;

    const float q1 = q, q2 = 0.5f * q, q3 = q * (1.0f / 3.0f);
    const float R64 = R * 0.015625f;

    if (wid == 0) {
        // ------- Riccati chain, t < T1 (data independent, starts NOW) ----
        float a = 100.0f, c = 100.0f, d = 0.0f;
        float E = 0.0f, F = 0.0f, G = g0 * 0.015625f;
        float is = 1.0f;
        const bool st = (lane == 0);
        for (int w = 0; w < NW1; ++w) {
            const bool exact = (w == 0);
            #pragma unroll 8
            for (int j = 0; j < WIN1; ++j) {
                float cp = c + q1;
                float dp = (d + c) + q2;
                float ap = fmaf(2.0f, d, a) + (c + q3);
                float Ep = E + F;
                float u1 = ap + Ep;
                float u2 = dp + F;
                float u3 = Ep + G;
                float Sv = (u1 + u3) + R64;
                if (exact) is = frcp(Sv);
                else       is = is * fmaf(-Sv, is, 2.0f);
                float k1 = u1 * is, k2 = u2 * is, k3 = u3 * is;
                a = fmaf(-k1, u1, ap);
                d = fmaf(-k1, u2, dp);
                c = fmaf(-k2, u2, cp);
                E = fmaf(-k1, u3, Ep);
                F = fmaf(-k2, u3, F);
                G = fmaf(-k3, u3, G);
                if (st) Gp[w * WIN1 + j] = make_float4(k1, k2, k3, is);
            }
            if (st) {
                if (w == 1) { s_fit[0] = a; s_fit[1] = d; s_fit[2] = c; } // tau=64
                if (w == 2) { s_fit[3] = a; s_fit[4] = d; s_fit[5] = c; } // tau=96
                if (w == 3) { s_fit[6] = a; s_fit[7] = d; s_fit[8] = c; } // tau=128
            }
            asm volatile("bar.sync 1, 64;" ::: "memory");
        }
    } else if (wid == 1) {
        // --- mean / loglik chain t < T1; ybar read directly from global ---
        const float2* gy = (const float2*)g_ybar;
        float m0 = 0.f, m1 = 0.f, V0 = 0.f, V1 = 0.f;
        float mV0 = 0.f, mV1 = 0.f, PV0 = 0.f, PV1 = 0.f;
        float llq = 0.f;
        for (int w = 0; w < NW1; ++w) {
            if ((w & 1) == 0) {                // windows 0,1 -> chunk0; 2,3 -> chunk1
                while (ldacq(&g_flagY[w >> 1]) == 0) {}
            }
            asm volatile("bar.sync 1, 64;" ::: "memory");
            const int tb = w * WIN1;
            #pragma unroll 8
            for (int j = 0; j < WIN1; ++j) {
                float4 g  = Gp[tb + j];
                float2 yb = gy[tb + j];
                float k12 = g.x + g.y;
                float km  = k12 + g.z;
                float Ib0 = yb.x - m0;
                float Ib1 = yb.y - m1;
                float vu0 = fmaf(g.y, Ib0, V0);
                float vu1 = fmaf(g.y, Ib1, V1);
                float mn0 = fmaf(km, Ib0, mV0);
                float mn1 = fmaf(km, Ib1, mV1);
                float Pn0 = fmaf(k12, Ib0, PV0);
                float Pn1 = fmaf(k12, Ib1, PV1);
                mV0 = mn0 + vu0;  mV1 = mn1 + vu1;
                PV0 = Pn0 + vu0;  PV1 = Pn1 + vu1;
                m0 = mn0;  m1 = mn1;
                V0 = vu0;  V1 = vu1;
                float ss = fmaf(Ib1, Ib1, Ib0 * Ib0);
                llq = fmaf(g.w, ss, llq);
            }
        }
        if (lane == 0) {
            s_pub[0] = m0; s_pub[1] = V0; s_pub[2] = PV0;
            s_pub[3] = m1; s_pub[4] = V1; s_pub[5] = PV1;
            s_pub[6] = llq;
        }
    }
    __syncthreads();

    // ------- wait for all ybar chunks (free by now), bulk stage -------
    if (tid == 0) { while (ldacq(&g_ctrA) < NCHK) {} }
    __syncthreads();
    {
        const float4* src = (const float4*)g_ybar;
        float4*       dst = (float4*)ybp;
        #pragma unroll
        for (int i = tid; i < 2 * T_STEPS / 4; i += 256) dst[i] = src[i];
    }

    // ------- phase 2a: fitted gains for t >= T1 + logdet partials -------
    {
        float4 fa = Gp[63], fb = Gp[95], fc = Gp[127];
        float ls = 0.0f;
        for (int t = tid; t < T_STEPS; t += 256) {
            float4 g;
            if (t >= T1) {
                float x  = frcp((float)(t + 1));
                float ea = x - XA, eb = x - XB, ec = x - XC;
                float L0 = eb * ec * IDA;
                float L1 = ea * ec * IDB;
                float L2 = ea * eb * IDC;
                g.x = fmaf(L0, fa.x, fmaf(L1, fb.x, L2 * fc.x));
                g.y = fmaf(L0, fa.y, fmaf(L1, fb.y, L2 * fc.y));
                g.z = fmaf(L0, fa.z, fmaf(L1, fb.z, L2 * fc.z));
                g.w = fmaf(L0, fa.w, fmaf(L1, fb.w, L2 * fc.w));
                Gp[t] = g;
            } else {
                g = Gp[t];
            }
            ls += __log2f(g.w);
        }
        #pragma unroll
        for (int m = 16; m; m >>= 1)
            ls += __shfl_xor_sync(0xffffffffu, ls, m);
        if (lane == 0) s_red[wid] = ls;          // s_red[0..7]
    }
    __syncthreads();

    // ---- phase 2b: compose per-chunk affine maps (s = (m, V, PV)) ----
    if (tid < CH2) {
        float c11 = 1.f, c21 = 0.f, c31 = 0.f;
        float c12 = 0.f, c22 = 1.f, c32 = 0.f;
        float bx1 = 0.f, bx2 = 0.f, bx3 = 0.f;
        float by1 = 0.f, by2 = 0.f, by3 = 0.f;
        const int base = T1 + tid * WIN2;
        #pragma unroll 4
        for (int j = 0; j < WIN2; ++j) {
            float4 g  = Gp[base + j];
            float2 yb = ybp[base + j];
            float k2v = g.y;
            float k12 = g.x + g.y;
            float km  = k12 + g.z;
            float k31 = k12 + k2v;
            {
                float n1 = fmaf(-km,  c11, c11 + c21);
                float n2 = fmaf(-k2v, c11, c21);
                float n3 = fmaf(-k31, c11, c21 + c31);
                c11 = n1; c21 = n2; c31 = n3;
            }
            {
                float n1 = fmaf(-km,  c12, c12 + c22);
                float n2 = fmaf(-k2v, c12, c22);
                float n3 = fmaf(-k31, c12, c22 + c32);
                c12 = n1; c22 = n2; c32 = n3;
            }
            {
                float n1 = fmaf(km,  yb.x, fmaf(-km,  bx1, bx1 + bx2));
                float n2 = fmaf(k2v, yb.x, fmaf(-k2v, bx1, bx2));
                float n3 = fmaf(k31, yb.x, fmaf(-k31, bx1, bx2 + bx3));
                bx1 = n1; bx2 = n2; bx3 = n3;
                float p1 = fmaf(km,  yb.y, fmaf(-km,  by1, by1 + by2));
                float p2 = fmaf(k2v, yb.y, fmaf(-k2v, by1, by2));
                float p3 = fmaf(k31, yb.y, fmaf(-k31, by1, by2 + by3));
                by1 = p1; by2 = p2; by3 = p3;
            }
        }
        float* r = s_cmp + tid * 12;
        r[0] = c11; r[1] = c21; r[2] = c31;
        r[3] = c12; r[4] = c22; r[5] = c32;
        r[6] = bx1; r[7] = bx2; r[8] = bx3;
        r[9] = by1; r[10] = by2; r[11] = by3;
    }
    __syncthreads();

    // -------- phase 2c: sequential combine across CH2 chunks --------
    if (tid == 0) {
        float m0 = s_pub[0], V0 = s_pub[1], PV0 = s_pub[2];
        float m1 = s_pub[3], V1 = s_pub[4], PV1 = s_pub[5];
        s_bnd[0] = m0; s_bnd[1] = V0; s_bnd[2] = PV0;
        s_bnd[3] = m1; s_bnd[4] = V1; s_bnd[5] = PV1;
        for (int k = 0; k < CH2; ++k) {
            const float* r = s_cmp + k * 12;
            float n0  = fmaf(r[0], m0, fmaf(r[3], V0, r[6]));
            float nV0 = fmaf(r[1], m0, fmaf(r[4], V0, r[7]));
            float nP0 = fmaf(r[2], m0, fmaf(r[5], V0, PV0 + r[8]));
            float n1  = fmaf(r[0], m1, fmaf(r[3], V1, r[9]));
            float nV1 = fmaf(r[1], m1, fmaf(r[4], V1, r[10]));
            float nP1 = fmaf(r[2], m1, fmaf(r[5], V1, PV1 + r[11]));
            m0 = n0; V0 = nV0; PV0 = nP0;
            m1 = n1; V1 = nV1; PV1 = nP1;
            float* b = s_bnd + (k + 1) * 6;
            b[0] = m0; b[1] = V0; b[2] = PV0;
            b[3] = m1; b[4] = V1; b[5] = PV1;
        }
    }
    __syncthreads();

    // -------- phase 2d: replay chunks for llq + final state --------
    float llq2d = 0.0f;
    if (tid < CH2) {
        const float* b = s_bnd + tid * 6;
        float m0 = b[0], V0 = b[1], PV0 = b[2];
        float m1 = b[3], V1 = b[4], PV1 = b[5];
        float mV0 = m0 + V0, mV1 = m1 + V1;
        float Pn0 = 0.f, Pn1 = 0.f;
        const int base = T1 + tid * WIN2;
        #pragma unroll 4
        for (int j = 0; j < WIN2; ++j) {
            float4 g  = Gp[base + j];
            float2 yb = ybp[base + j];
            float k12 = g.x + g.y;
            float km  = k12 + g.z;
            float Ib0 = yb.x - m0;
            float Ib1 = yb.y - m1;
            float vu0 = fmaf(g.y, Ib0, V0);
            float vu1 = fmaf(g.y, Ib1, V1);
            float mn0 = fmaf(km, Ib0, mV0);
            float mn1 = fmaf(km, Ib1, mV1);
            Pn0 = fmaf(k12, Ib0, PV0);
            Pn1 = fmaf(k12, Ib1, PV1);
            mV0 = mn0 + vu0;  mV1 = mn1 + vu1;
            PV0 = Pn0 + vu0;  PV1 = Pn1 + vu1;
            m0 = mn0;  m1 = mn1;
            V0 = vu0;  V1 = vu1;
            float ss = fmaf(Ib1, Ib1, Ib0 * Ib0);
            llq2d = fmaf(g.w, ss, llq2d);
        }
        if (tid == CH2 - 1) {
            s_pub[8]  = Pn0 - V0;  s_pub[9]  = Pn1 - V1;   // posterior pos
            s_pub[10] = V0;        s_pub[11] = V1;          // posterior vel
        }
    }
    #pragma unroll
    for (int m = 16; m; m >>= 1)
        llq2d += __shfl_xor_sync(0xffffffffu, llq2d, m);
    if (lane == 0) s_red[8 + wid] = llq2d;       // s_red[8..15]

    // -------- wait sensor partials, reduce (full-MLP) --------
    if (tid == 0) { while (ldacq(&g_ctrC) < NCHK) {} }
    __syncthreads();
    {
        float accs = 0.0f;
        if (tid < OBS) {
            const float* ap = g_accp + tid;
            float a0 = 0.f, a1 = 0.f, a2 = 0.f, a3 = 0.f;
            #pragma unroll
            for (int k = 0; k < NCHK; k += 4) {
                a0 += ap[(k    ) * OBS];
                a1 += ap[(k + 1) * OBS];
                a2 += ap[(k + 2) * OBS];
                a3 += ap[(k + 3) * OBS];
            }
            accs = (a0 + a1) + (a2 + a3);
        }
        #pragma unroll
        for (int m = 16; m; m >>= 1)
            accs += __shfl_xor_sync(0xffffffffu, accs, m);
        if (lane == 0) s_red[16 + wid] = accs;   // s_red[16..23]
    }
    // reset global sync state for the next graph replay
    if (tid < NCHK) g_flagY[tid] = 0;
    if (tid == 200) g_ctrA = 0;
    if (tid == 201) g_ctrB = 0;
    if (tid == 202) g_ctrC = 0;
    __syncthreads();

    if (tid == 0) {
        float lsum = 0.f, llq = s_pub[6], atot = 0.f;
        #pragma unroll
        for (int i = 0; i < 8; ++i) {
            lsum += s_red[i];
            llq  += s_red[8 + i];
            atot += s_red[16 + i];
        }
        // covariance at T via Lagrange extrapolation to x = 1/4096
        float x  = 1.0f / 4096.0f;
        float ea = x - XA, eb = x - XB, ec = x - XC;
        float L0 = eb * ec * IDA;
        float L1 = ea * ec * IDB;
        float L2 = ea * eb * IDC;
        float a = fmaf(L0, s_fit[0], fmaf(L1, s_fit[3], L2 * s_fit[6]));
        float d = fmaf(L0, s_fit[1], fmaf(L1, s_fit[4], L2 * s_fit[7]));
        float c = fmaf(L0, s_fit[2], fmaf(L1, s_fit[5], L2 * s_fit[8]));

        double ldS = -(double)lsum;
        double ldA = (double)(T_STEPS - 1) * log2((double)R)
                   + log2((double)R + (double)T_STEPS * (double)g0);
        double ld  = 63.0 * ldA + ldS + 6.0 * (double)T_STEPS;
        const double LN2    = 0.6931471805599453094;
        const double LOG2PI = 1.8378770664093454836;
        double quad = 0.5 * ((double)atot + (double)llq);
        double logp = -quad - ld * LN2 - 64.0 * (double)T_STEPS * LOG2PI;
        out[0] = (float)logp;
        out[1] = s_pub[8];  out[2] = s_pub[9];
        out[3] = s_pub[10]; out[4] = s_pub[11];
        out[5]  = a;   out[6]  = 0.f; out[7]  = d;   out[8]  = 0.f;
        out[9]  = 0.f; out[10] = a;   out[11] = 0.f; out[12] = d;
        out[13] = d;   out[14] = 0.f; out[15] = c;   out[16] = 0.f;
        out[17] = 0.f; out[18] = d;   out[19] = 0.f; out[20] = c;
    }
}

extern "C" void kernel_launch(void* const* d_in, const int* in_sizes, int n_in,
                              void* d_out, int out_size) {
    const float* obs = (const float*)d_in[0];
    const float* lbs = (const float*)d_in[1];
    const float* lon = (const float*)d_in[2];
    const float* ltn = (const float*)d_in[3];
    float* out = (float*)d_out;
    (void)in_sizes; (void)n_in; (void)out_size;

    static bool attr_set = false;
    if (!attr_set) {
        cudaFuncSetAttribute(fused_kernel,
                             cudaFuncAttributeMaxDynamicSharedMemorySize,
                             SMEM_BYTES);
        attr_set = true;
    }
    fused_kernel<<<NCHK + 1, 256, SMEM_BYTES>>>(
        (const float4*)obs, lbs, lon, ltn, out);
}

// round 12
// speedup vs baseline: 1.0790x; 1.0790x over previous
#include <cuda_runtime.h>

// Kalman: NCV(4) + 128 static sensor biases, T=4096.
// Round 12: test DRAM-MLP hypothesis. Identical math to round 10/11
// (rel_err must be bit-identical); two scheduling changes only:
//  1. Worker step1 batches all 8 LDG.128 into registers BEFORE the
//     STS/shfl-reduce loop (8 loads in flight per thread).
//  2. Master runs phase 2a (gain fill, no ybar dependency) before the
//     ctrA wait + ybar staging.

#define T_STEPS 4096
#define OBS 128
#define T1 128
#define WIN1 32
#define NW1 (T1 / WIN1)               // 4
#define WIN2 32
#define CH2 ((T_STEPS - T1) / WIN2)   // 124
#define NCHK 64                        // worker chunks (64 steps each)

__device__ float g_ybar[2 * T_STEPS];
__device__ float g_csum[NCHK * OBS];
__device__ float g_accp[NCHK * OBS];
__device__ int   g_flagY[NCHK];
__device__ int   g_ctrA, g_ctrB, g_ctrC;

__device__ __forceinline__ float frcp(float x) {
    float r;
    asm("rcp.approx.f32 %0, %1;" : "=f"(r) : "f"(x));
    return r;
}
__device__ __forceinline__ int ldacq(const int* p) {
    int v;
    asm volatile("ld.acquire.gpu.s32 %0, [%1];" : "=r"(v) : "l"(p) : "memory");
    return v;
}
__device__ __forceinline__ void strel(int* p, int v) {
    asm volatile("st.release.gpu.s32 [%0], %1;" :: "l"(p), "r"(v) : "memory");
}

// ---- master smem layout (float offsets) ----
#define OFF_G    0            // float4[4096]  -> 16384
#define OFF_YB   16384        // float2[4096]  ->  8192
#define OFF_BND  24576        // (CH2+1)*6 = 750 -> 752
#define OFF_CMP  25328        // CH2*12 = 1488
#define OFF_RED  26816        // 32
#define OFF_FIT  26848        // 16
#define OFF_PUB  26864        // 16
#define SMEM_FLOATS 26880
#define SMEM_BYTES  (SMEM_FLOATS * 4)

// Lagrange nodes x = 1/tau at tau = 64, 96, 128
#define XA (1.0f / 64.0f)
#define XB (1.0f / 96.0f)
#define XC (1.0f / 128.0f)
#define IDA (  24576.0f)
#define IDB ( -73728.0f)
#define IDC (  49152.0f)

__global__ void __launch_bounds__(256, 1) fused_kernel(
    const float4* __restrict__ obs4,
    const float* __restrict__ lbs,
    const float* __restrict__ lon,
    const float* __restrict__ ltn,
    float* __restrict__ out)
{
    extern __shared__ float smem[];
    const int tid  = threadIdx.x;
    const int bid  = blockIdx.x;
    const int wid  = tid >> 5;
    const int lane = tid & 31;

    const float R  = expf(2.0f * lon[0]);
    const float q  = expf(2.0f * ltn[0]);
    const float g0 = expf(2.0f * lbs[0]);

    if (bid < NCHK) {
        // ==================== WORKER block: chunk bid ====================
        float* tile = smem;            // [64][128] floats (32 KB)
        float* yloc = smem + 8192;     // [2*64]
        float* itg  = smem + 8320;     // [64]
        float* iaT  = smem + 8384;     // [64]
        const int c  = bid;
        const int c0 = c * 64;

        // step 1a: BATCH all 8 global loads (full MLP)
        float4 v[8];
        #pragma unroll
        for (int k = 0; k < 8; ++k)
            v[k] = obs4[(c0 + wid * 8 + k) * 32 + lane];

        // step 1b: store tile + ybar reductions
        #pragma unroll
        for (int k = 0; k < 8; ++k) {
            int tl = wid * 8 + k;
            int t  = c0 + tl;
            ((float4*)tile)[tl * 32 + lane] = v[k];
            float s = (v[k].x + v[k].y) + (v[k].z + v[k].w);
            #pragma unroll
            for (int m = 8; m; m >>= 1)
                s += __shfl_xor_sync(0xffffffffu, s, m);
            s *= 0.015625f;
            if (lane == 0)  { yloc[2 * tl]     = s; g_ybar[2 * t]     = s; }
            if (lane == 16) { yloc[2 * tl + 1] = s; g_ybar[2 * t + 1] = s; }
        }
        if (tid < 64) {
            int t = c0 + tid;
            float den0 = fmaf((float)t, g0, R);
            float den1 = den0 + g0;
            itg[tid] = g0 * frcp(den0);
            iaT[tid] = den0 * frcp(den1) * frcp(R);
        }
        __syncthreads();
        if (tid == 0) {
            strel(&g_flagY[c], 1);             // publish ybar chunk
            __threadfence();
            atomicAdd(&g_ctrA, 1);
        }

        // step 2: per-sensor chunk sums
        if (tid < OBS) {
            const int comp = tid >> 6;
            float cs = 0.0f;
            #pragma unroll 8
            for (int i = 0; i < 64; ++i)
                cs += tile[i * OBS + tid] - yloc[2 * i + comp];
            g_csum[c * OBS + tid] = cs;
        }
        __syncthreads();
        if (tid == 0) {
            __threadfence();
            atomicAdd(&g_ctrB, 1);
            while (ldacq(&g_ctrB) < NCHK) {}
        }
        __syncthreads();

        // step 3: exclusive prefix (full-MLP, predicated) + replay partial
        if (tid < OBS) {
            const float* cp = g_csum + tid;
            float p0 = 0.f, p1 = 0.f, p2 = 0.f, p3 = 0.f;
            #pragma unroll
            for (int k = 0; k < NCHK; k += 4) {
                if (k     < c) p0 += cp[(k    ) * OBS];
                if (k + 1 < c) p1 += cp[(k + 1) * OBS];
                if (k + 2 < c) p2 += cp[(k + 2) * OBS];
                if (k + 3 < c) p3 += cp[(k + 3) * OBS];
            }
            float S = (p0 + p1) + (p2 + p3);
            const int comp = tid >> 6;
            float acc = 0.0f;
            #pragma unroll 8
            for (int i = 0; i < 64; ++i) {
                float x  = tile[i * OBS + tid] - yloc[2 * i + comp];
                float rt = fmaf(-S, itg[i], x);
                S += x;
                acc = fmaf(iaT[i], rt * rt, acc);
            }
            g_accp[c * OBS + tid] = acc;
        }
        __syncthreads();
        if (tid == 0) { __threadfence(); atomicAdd(&g_ctrC, 1); }
        return;
    }

    // ======================= MASTER block =======================
    float4* Gp    = (float4*)(smem + OFF_G);
    float2* ybp   = (float2*)(smem + OFF_YB);
    float*  s_bnd = smem + OFF_BND;
    float*  s_cmp = smem + OFF_CMP;
    float*  s_red = smem + OFF_RED;
    float*  s_fit = smem + OFF_FIT;
    float*  s_pub = smem + OFF_PUB;

    const float q1 = q, q2 = 0.5f * q, q3 = q * (1.0f / 3.0f);
    const float R64 = R * 0.015625f;

    if (wid == 0) {
        // ------- Riccati chain, t < T1 (data independent, starts NOW) ----
        float a = 100.0f, c = 100.0f, d = 0.0f;
        float E = 0.0f, F = 0.0f, G = g0 * 0.015625f;
        float is = 1.0f;
        const bool st = (lane == 0);
        for (int w = 0; w < NW1; ++w) {
            const bool exact = (w == 0);
            #pragma unroll 8
            for (int j = 0; j < WIN1; ++j) {
                float cp = c + q1;
                float dp = (d + c) + q2;
                float ap = fmaf(2.0f, d, a) + (c + q3);
                float Ep = E + F;
                float u1 = ap + Ep;
                float u2 = dp + F;
                float u3 = Ep + G;
                float Sv = (u1 + u3) + R64;
                if (exact) is = frcp(Sv);
                else       is = is * fmaf(-Sv, is, 2.0f);
                float k1 = u1 * is, k2 = u2 * is, k3 = u3 * is;
                a = fmaf(-k1, u1, ap);
                d = fmaf(-k1, u2, dp);
                c = fmaf(-k2, u2, cp);
                E = fmaf(-k1, u3, Ep);
                F = fmaf(-k2, u3, F);
                G = fmaf(-k3, u3, G);
                if (st) Gp[w * WIN1 + j] = make_float4(k1, k2, k3, is);
            }
            if (st) {
                if (w == 1) { s_fit[0] = a; s_fit[1] = d; s_fit[2] = c; } // tau=64
                if (w == 2) { s_fit[3] = a; s_fit[4] = d; s_fit[5] = c; } // tau=96
                if (w == 3) { s_fit[6] = a; s_fit[7] = d; s_fit[8] = c; } // tau=128
            }
            asm volatile("bar.sync 1, 64;" ::: "memory");
        }
    } else if (wid == 1) {
        // --- mean / loglik chain t < T1; ybar read directly from global ---
        const float2* gy = (const float2*)g_ybar;
        float m0 = 0.f, m1 = 0.f, V0 = 0.f, V1 = 0.f;
        float mV0 = 0.f, mV1 = 0.f, PV0 = 0.f, PV1 = 0.f;
        float llq = 0.f;
        for (int w = 0; w < NW1; ++w) {
            if ((w & 1) == 0) {                // windows 0,1 -> chunk0; 2,3 -> chunk1
                while (ldacq(&g_flagY[w >> 1]) == 0) {}
            }
            asm volatile("bar.sync 1, 64;" ::: "memory");
            const int tb = w * WIN1;
            #pragma unroll 8
            for (int j = 0; j < WIN1; ++j) {
                float4 g  = Gp[tb + j];
                float2 yb = gy[tb + j];
                float k12 = g.x + g.y;
                float km  = k12 + g.z;
                float Ib0 = yb.x - m0;
                float Ib1 = yb.y - m1;
                float vu0 = fmaf(g.y, Ib0, V0);
                float vu1 = fmaf(g.y, Ib1, V1);
                float mn0 = fmaf(km, Ib0, mV0);
                float mn1 = fmaf(km, Ib1, mV1);
                float Pn0 = fmaf(k12, Ib0, PV0);
                float Pn1 = fmaf(k12, Ib1, PV1);
                mV0 = mn0 + vu0;  mV1 = mn1 + vu1;
                PV0 = Pn0 + vu0;  PV1 = Pn1 + vu1;
                m0 = mn0;  m1 = mn1;
                V0 = vu0;  V1 = vu1;
                float ss = fmaf(Ib1, Ib1, Ib0 * Ib0);
                llq = fmaf(g.w, ss, llq);
            }
        }
        if (lane == 0) {
            s_pub[0] = m0; s_pub[1] = V0; s_pub[2] = PV0;
            s_pub[3] = m1; s_pub[4] = V1; s_pub[5] = PV1;
            s_pub[6] = llq;
        }
    }
    __syncthreads();

    // ------- phase 2a FIRST (no ybar dependency): gain fill + logdet -----
    {
        float4 fa = Gp[63], fb = Gp[95], fc = Gp[127];
        float ls = 0.0f;
        for (int t = tid; t < T_STEPS; t += 256) {
            float4 g;
            if (t >= T1) {
                float x  = frcp((float)(t + 1));
                float ea = x - XA, eb = x - XB, ec = x - XC;
                float L0 = eb * ec * IDA;
                float L1 = ea * ec * IDB;
                float L2 = ea * eb * IDC;
                g.x = fmaf(L0, fa.x, fmaf(L1, fb.x, L2 * fc.x));
                g.y = fmaf(L0, fa.y, fmaf(L1, fb.y, L2 * fc.y));
                g.z = fmaf(L0, fa.z, fmaf(L1, fb.z, L2 * fc.z));
                g.w = fmaf(L0, fa.w, fmaf(L1, fb.w, L2 * fc.w));
                Gp[t] = g;
            } else {
                g = Gp[t];
            }
            ls += __log2f(g.w);
        }
        #pragma unroll
        for (int m = 16; m; m >>= 1)
            ls += __shfl_xor_sync(0xffffffffu, ls, m);
        if (lane == 0) s_red[wid] = ls;          // s_red[0..7]
    }

    // ------- now wait for all ybar chunks, bulk stage -------
    if (tid == 0) { while (ldacq(&g_ctrA) < NCHK) {} }
    __syncthreads();
    {
        const float4* src = (const float4*)g_ybar;
        float4*       dst = (float4*)ybp;
        #pragma unroll
        for (int i = tid; i < 2 * T_STEPS / 4; i += 256) dst[i] = src[i];
    }
    __syncthreads();

    // ---- phase 2b: compose per-chunk affine maps (s = (m, V, PV)) ----
    if (tid < CH2) {
        float c11 = 1.f, c21 = 0.f, c31 = 0.f;
        float c12 = 0.f, c22 = 1.f, c32 = 0.f;
        float bx1 = 0.f, bx2 = 0.f, bx3 = 0.f;
        float by1 = 0.f, by2 = 0.f, by3 = 0.f;
        const int base = T1 + tid * WIN2;
        #pragma unroll 4
        for (int j = 0; j < WIN2; ++j) {
            float4 g  = Gp[base + j];
            float2 yb = ybp[base + j];
            float k2v = g.y;
            float k12 = g.x + g.y;
            float km  = k12 + g.z;
            float k31 = k12 + k2v;
            {
                float n1 = fmaf(-km,  c11, c11 + c21);
                float n2 = fmaf(-k2v, c11, c21);
                float n3 = fmaf(-k31, c11, c21 + c31);
                c11 = n1; c21 = n2; c31 = n3;
            }
            {
                float n1 = fmaf(-km,  c12, c12 + c22);
                float n2 = fmaf(-k2v, c12, c22);
                float n3 = fmaf(-k31, c12, c22 + c32);
                c12 = n1; c22 = n2; c32 = n3;
            }
            {
                float n1 = fmaf(km,  yb.x, fmaf(-km,  bx1, bx1 + bx2));
                float n2 = fmaf(k2v, yb.x, fmaf(-k2v, bx1, bx2));
                float n3 = fmaf(k31, yb.x, fmaf(-k31, bx1, bx2 + bx3));
                bx1 = n1; bx2 = n2; bx3 = n3;
                float p1 = fmaf(km,  yb.y, fmaf(-km,  by1, by1 + by2));
                float p2 = fmaf(k2v, yb.y, fmaf(-k2v, by1, by2));
                float p3 = fmaf(k31, yb.y, fmaf(-k31, by1, by2 + by3));
                by1 = p1; by2 = p2; by3 = p3;
            }
        }
        float* r = s_cmp + tid * 12;
        r[0] = c11; r[1] = c21; r[2] = c31;
        r[3] = c12; r[4] = c22; r[5] = c32;
        r[6] = bx1; r[7] = bx2; r[8] = bx3;
        r[9] = by1; r[10] = by2; r[11] = by3;
    }
    __syncthreads();

    // -------- phase 2c: sequential combine across CH2 chunks --------
    if (tid == 0) {
        float m0 = s_pub[0], V0 = s_pub[1], PV0 = s_pub[2];
        float m1 = s_pub[3], V1 = s_pub[4], PV1 = s_pub[5];
        s_bnd[0] = m0; s_bnd[1] = V0; s_bnd[2] = PV0;
        s_bnd[3] = m1; s_bnd[4] = V1; s_bnd[5] = PV1;
        for (int k = 0; k < CH2; ++k) {
            const float* r = s_cmp + k * 12;
            float n0  = fmaf(r[0], m0, fmaf(r[3], V0, r[6]));
            float nV0 = fmaf(r[1], m0, fmaf(r[4], V0, r[7]));
            float nP0 = fmaf(r[2], m0, fmaf(r[5], V0, PV0 + r[8]));
            float n1  = fmaf(r[0], m1, fmaf(r[3], V1, r[9]));
            float nV1 = fmaf(r[1], m1, fmaf(r[4], V1, r[10]));
            float nP1 = fmaf(r[2], m1, fmaf(r[5], V1, PV1 + r[11]));
            m0 = n0; V0 = nV0; PV0 = nP0;
            m1 = n1; V1 = nV1; PV1 = nP1;
            float* b = s_bnd + (k + 1) * 6;
            b[0] = m0; b[1] = V0; b[2] = PV0;
            b[3] = m1; b[4] = V1; b[5] = PV1;
        }
    }
    __syncthreads();

    // -------- phase 2d: replay chunks for llq + final state --------
    float llq2d = 0.0f;
    if (tid < CH2) {
        const float* b = s_bnd + tid * 6;
        float m0 = b[0], V0 = b[1], PV0 = b[2];
        float m1 = b[3], V1 = b[4], PV1 = b[5];
        float mV0 = m0 + V0, mV1 = m1 + V1;
        float Pn0 = 0.f, Pn1 = 0.f;
        const int base = T1 + tid * WIN2;
        #pragma unroll 4
        for (int j = 0; j < WIN2; ++j) {
            float4 g  = Gp[base + j];
            float2 yb = ybp[base + j];
            float k12 = g.x + g.y;
            float km  = k12 + g.z;
            float Ib0 = yb.x - m0;
            float Ib1 = yb.y - m1;
            float vu0 = fmaf(g.y, Ib0, V0);
            float vu1 = fmaf(g.y, Ib1, V1);
            float mn0 = fmaf(km, Ib0, mV0);
            float mn1 = fmaf(km, Ib1, mV1);
            Pn0 = fmaf(k12, Ib0, PV0);
            Pn1 = fmaf(k12, Ib1, PV1);
            mV0 = mn0 + vu0;  mV1 = mn1 + vu1;
            PV0 = Pn0 + vu0;  PV1 = Pn1 + vu1;
            m0 = mn0;  m1 = mn1;
            V0 = vu0;  V1 = vu1;
            float ss = fmaf(Ib1, Ib1, Ib0 * Ib0);
            llq2d = fmaf(g.w, ss, llq2d);
        }
        if (tid == CH2 - 1) {
            s_pub[8]  = Pn0 - V0;  s_pub[9]  = Pn1 - V1;   // posterior pos
            s_pub[10] = V0;        s_pub[11] = V1;          // posterior vel
        }
    }
    #pragma unroll
    for (int m = 16; m; m >>= 1)
        llq2d += __shfl_xor_sync(0xffffffffu, llq2d, m);
    if (lane == 0) s_red[8 + wid] = llq2d;       // s_red[8..15]

    // -------- wait sensor partials, reduce (full-MLP) --------
    if (tid == 0) { while (ldacq(&g_ctrC) < NCHK) {} }
    __syncthreads();
    {
        float accs = 0.0f;
        if (tid < OBS) {
            const float* ap = g_accp + tid;
            float a0 = 0.f, a1 = 0.f, a2 = 0.f, a3 = 0.f;
            #pragma unroll
            for (int k = 0; k < NCHK; k += 4) {
                a0 += ap[(k    ) * OBS];
                a1 += ap[(k + 1) * OBS];
                a2 += ap[(k + 2) * OBS];
                a3 += ap[(k + 3) * OBS];
            }
            accs = (a0 + a1) + (a2 + a3);
        }
        #pragma unroll
        for (int m = 16; m; m >>= 1)
            accs += __shfl_xor_sync(0xffffffffu, accs, m);
        if (lane == 0) s_red[16 + wid] = accs;   // s_red[16..23]
    }
    // reset global sync state for the next graph replay
    if (tid < NCHK) g_flagY[tid] = 0;
    if (tid == 200) g_ctrA = 0;
    if (tid == 201) g_ctrB = 0;
    if (tid == 202) g_ctrC = 0;
    __syncthreads();

    if (tid == 0) {
        float lsum = 0.f, llq = s_pub[6], atot = 0.f;
        #pragma unroll
        for (int i = 0; i < 8; ++i) {
            lsum += s_red[i];
            llq  += s_red[8 + i];
            atot += s_red[16 + i];
        }
        // covariance at T via Lagrange extrapolation to x = 1/4096
        float x  = 1.0f / 4096.0f;
        float ea = x - XA, eb = x - XB, ec = x - XC;
        float L0 = eb * ec * IDA;
        float L1 = ea * ec * IDB;
        float L2 = ea * eb * IDC;
        float a = fmaf(L0, s_fit[0], fmaf(L1, s_fit[3], L2 * s_fit[6]));
        float d = fmaf(L0, s_fit[1], fmaf(L1, s_fit[4], L2 * s_fit[7]));
        float c = fmaf(L0, s_fit[2], fmaf(L1, s_fit[5], L2 * s_fit[8]));

        double ldS = -(double)lsum;
        double ldA = (double)(T_STEPS - 1) * log2((double)R)
                   + log2((double)R + (double)T_STEPS * (double)g0);
        double ld  = 63.0 * ldA + ldS + 6.0 * (double)T_STEPS;
        const double LN2    = 0.6931471805599453094;
        const double LOG2PI = 1.8378770664093454836;
        double quad = 0.5 * ((double)atot + (double)llq);
        double logp = -quad - ld * LN2 - 64.0 * (double)T_STEPS * LOG2PI;
        out[0] = (float)logp;
        out[1] = s_pub[8];  out[2] = s_pub[9];
        out[3] = s_pub[10]; out[4] = s_pub[11];
        out[5]  = a;   out[6]  = 0.f; out[7]  = d;   out[8]  = 0.f;
        out[9]  = 0.f; out[10] = a;   out[11] = 0.f; out[12] = d;
        out[13] = d;   out[14] = 0.f; out[15] = c;   out[16] = 0.f;
        out[17] = 0.f; out[18] = d;   out[19] = 0.f; out[20] = c;
    }
}

extern "C" void kernel_launch(void* const* d_in, const int* in_sizes, int n_in,
                              void* d_out, int out_size) {
    const float* obs = (const float*)d_in[0];
    const float* lbs = (const float*)d_in[1];
    const float* lon = (const float*)d_in[2];
    const float* ltn = (const float*)d_in[3];
    float* out = (float*)d_out;
    (void)in_sizes; (void)n_in; (void)out_size;

    static bool attr_set = false;
    if (!attr_set) {
        cudaFuncSetAttribute(fused_kernel,
                             cudaFuncAttributeMaxDynamicSharedMemorySize,
                             SMEM_BYTES);
        attr_set = true;
    }
    fused_kernel<<<NCHK + 1, 256, SMEM_BYTES>>>(
        (const float4*)obs, lbs, lon, ltn, out);
}

// round 13
// speedup vs baseline: 1.2799x; 1.1862x over previous
#include <cuda_runtime.h>

// Kalman: NCV(4) + 128 static sensor biases, T=4096.
// Round 13: cut master critical-path cycles.
//  - T1=64 (serial Riccati/mean only 64 steps; Lagrange nodes tau=32/48/64).
//  - Phase 2c serial chunk-combine replaced by Kogge-Stone scan over the
//    126 per-chunk affine maps (associative compose, 7 rounds, parallel).
// Workers unchanged from round 12 (batched MLP loads validated).

#define T_STEPS 4096
#define OBS 128
#define T1 64
#define WIN1 16
#define NW1 (T1 / WIN1)               // 4
#define WIN2 32
#define CH2 ((T_STEPS - T1) / WIN2)   // 126
#define NCHK 64                        // worker chunks (64 steps each)

__device__ float g_ybar[2 * T_STEPS];
__device__ float g_csum[NCHK * OBS];
__device__ float g_accp[NCHK * OBS];
__device__ int   g_flagY[NCHK];
__device__ int   g_ctrA, g_ctrB, g_ctrC;

__device__ __forceinline__ float frcp(float x) {
    float r;
    asm("rcp.approx.f32 %0, %1;" : "=f"(r) : "f"(x));
    return r;
}
__device__ __forceinline__ int ldacq(const int* p) {
    int v;
    asm volatile("ld.acquire.gpu.s32 %0, [%1];" : "=r"(v) : "l"(p) : "memory");
    return v;
}
__device__ __forceinline__ void strel(int* p, int v) {
    asm volatile("st.release.gpu.s32 [%0], %1;" :: "l"(p), "r"(v) : "memory");
}

// ---- master smem layout (float offsets) ----
#define OFF_G    0            // float4[4096]  -> 16384
#define OFF_YB   16384        // float2[4096]  ->  8192
#define OFF_CMPA 24576        // 126*12 = 1512
#define OFF_CMPB 26088        // 126*12 = 1512
#define OFF_RED  27600        // 32
#define OFF_FIT  27632        // 16
#define OFF_PUB  27648        // 16
#define SMEM_FLOATS 27664
#define SMEM_BYTES  (SMEM_FLOATS * 4)

// Lagrange nodes x = 1/tau at tau = 32, 48, 64
#define XA (1.0f / 32.0f)
#define XB (1.0f / 48.0f)
#define XC (1.0f / 64.0f)
#define IDA (  6144.0f)
#define IDB (-18432.0f)
#define IDC ( 12288.0f)

__global__ void __launch_bounds__(256, 1) fused_kernel(
    const float4* __restrict__ obs4,
    const float* __restrict__ lbs,
    const float* __restrict__ lon,
    const float* __restrict__ ltn,
    float* __restrict__ out)
{
    extern __shared__ float smem[];
    const int tid  = threadIdx.x;
    const int bid  = blockIdx.x;
    const int wid  = tid >> 5;
    const int lane = tid & 31;

    const float R  = expf(2.0f * lon[0]);
    const float q  = expf(2.0f * ltn[0]);
    const float g0 = expf(2.0f * lbs[0]);

    if (bid < NCHK) {
        // ==================== WORKER block: chunk bid ====================
        float* tile = smem;            // [64][128] floats (32 KB)
        float* yloc = smem + 8192;     // [2*64]
        float* itg  = smem + 8320;     // [64]
        float* iaT  = smem + 8384;     // [64]
        const int c  = bid;
        const int c0 = c * 64;

        // step 1a: batch all 8 global loads (full MLP)
        float4 v[8];
        #pragma unroll
        for (int k = 0; k < 8; ++k)
            v[k] = obs4[(c0 + wid * 8 + k) * 32 + lane];

        // step 1b: store tile + ybar reductions
        #pragma unroll
        for (int k = 0; k < 8; ++k) {
            int tl = wid * 8 + k;
            int t  = c0 + tl;
            ((float4*)tile)[tl * 32 + lane] = v[k];
            float s = (v[k].x + v[k].y) + (v[k].z + v[k].w);
            #pragma unroll
            for (int m = 8; m; m >>= 1)
                s += __shfl_xor_sync(0xffffffffu, s, m);
            s *= 0.015625f;
            if (lane == 0)  { yloc[2 * tl]     = s; g_ybar[2 * t]     = s; }
            if (lane == 16) { yloc[2 * tl + 1] = s; g_ybar[2 * t + 1] = s; }
        }
        if (tid < 64) {
            int t = c0 + tid;
            float den0 = fmaf((float)t, g0, R);
            float den1 = den0 + g0;
            itg[tid] = g0 * frcp(den0);
            iaT[tid] = den0 * frcp(den1) * frcp(R);
        }
        __syncthreads();
        if (tid == 0) {
            strel(&g_flagY[c], 1);
            __threadfence();
            atomicAdd(&g_ctrA, 1);
        }

        // step 2: per-sensor chunk sums
        if (tid < OBS) {
            const int comp = tid >> 6;
            float cs = 0.0f;
            #pragma unroll 8
            for (int i = 0; i < 64; ++i)
                cs += tile[i * OBS + tid] - yloc[2 * i + comp];
            g_csum[c * OBS + tid] = cs;
        }
        __syncthreads();
        if (tid == 0) {
            __threadfence();
            atomicAdd(&g_ctrB, 1);
            while (ldacq(&g_ctrB) < NCHK) {}
        }
        __syncthreads();

        // step 3: exclusive prefix (full-MLP, predicated) + replay partial
        if (tid < OBS) {
            const float* cp = g_csum + tid;
            float p0 = 0.f, p1 = 0.f, p2 = 0.f, p3 = 0.f;
            #pragma unroll
            for (int k = 0; k < NCHK; k += 4) {
                if (k     < c) p0 += cp[(k    ) * OBS];
                if (k + 1 < c) p1 += cp[(k + 1) * OBS];
                if (k + 2 < c) p2 += cp[(k + 2) * OBS];
                if (k + 3 < c) p3 += cp[(k + 3) * OBS];
            }
            float S = (p0 + p1) + (p2 + p3);
            const int comp = tid >> 6;
            float acc = 0.0f;
            #pragma unroll 8
            for (int i = 0; i < 64; ++i) {
                float x  = tile[i * OBS + tid] - yloc[2 * i + comp];
                float rt = fmaf(-S, itg[i], x);
                S += x;
                acc = fmaf(iaT[i], rt * rt, acc);
            }
            g_accp[c * OBS + tid] = acc;
        }
        __syncthreads();
        if (tid == 0) { __threadfence(); atomicAdd(&g_ctrC, 1); }
        return;
    }

    // ======================= MASTER block =======================
    float4* Gp    = (float4*)(smem + OFF_G);
    float2* ybp   = (float2*)(smem + OFF_YB);
    float*  cmpA  = smem + OFF_CMPA;
    float*  cmpB  = smem + OFF_CMPB;
    float*  s_red = smem + OFF_RED;
    float*  s_fit = smem + OFF_FIT;
    float*  s_pub = smem + OFF_PUB;

    const float q1 = q, q2 = 0.5f * q, q3 = q * (1.0f / 3.0f);
    const float R64 = R * 0.015625f;

    if (wid == 0) {
        // ------- Riccati chain, t < T1 (starts immediately) ----
        float a = 100.0f, c = 100.0f, d = 0.0f;
        float E = 0.0f, F = 0.0f, G = g0 * 0.015625f;
        float is = 1.0f;
        const bool st = (lane == 0);
        for (int w = 0; w < NW1; ++w) {
            const bool exact = (w == 0);
            #pragma unroll 8
            for (int j = 0; j < WIN1; ++j) {
                float cp = c + q1;
                float dp = (d + c) + q2;
                float ap = fmaf(2.0f, d, a) + (c + q3);
                float Ep = E + F;
                float u1 = ap + Ep;
                float u2 = dp + F;
                float u3 = Ep + G;
                float Sv = (u1 + u3) + R64;
                if (exact) is = frcp(Sv);
                else       is = is * fmaf(-Sv, is, 2.0f);
                float k1 = u1 * is, k2 = u2 * is, k3 = u3 * is;
                a = fmaf(-k1, u1, ap);
                d = fmaf(-k1, u2, dp);
                c = fmaf(-k2, u2, cp);
                E = fmaf(-k1, u3, Ep);
                F = fmaf(-k2, u3, F);
                G = fmaf(-k3, u3, G);
                if (st) Gp[w * WIN1 + j] = make_float4(k1, k2, k3, is);
            }
            if (st) {
                if (w == 1) { s_fit[0] = a; s_fit[1] = d; s_fit[2] = c; } // tau=32
                if (w == 2) { s_fit[3] = a; s_fit[4] = d; s_fit[5] = c; } // tau=48
                if (w == 3) { s_fit[6] = a; s_fit[7] = d; s_fit[8] = c; } // tau=64
            }
            asm volatile("bar.sync 1, 64;" ::: "memory");
        }
    } else if (wid == 1) {
        // --- mean / loglik chain t < T1 (all in worker chunk 0) ---
        const float2* gy = (const float2*)g_ybar;
        float m0 = 0.f, m1 = 0.f, V0 = 0.f, V1 = 0.f;
        float mV0 = 0.f, mV1 = 0.f, PV0 = 0.f, PV1 = 0.f;
        float llq = 0.f;
        for (int w = 0; w < NW1; ++w) {
            if (w == 0) { while (ldacq(&g_flagY[0]) == 0) {} }
            asm volatile("bar.sync 1, 64;" ::: "memory");
            const int tb = w * WIN1;
            #pragma unroll 8
            for (int j = 0; j < WIN1; ++j) {
                float4 g  = Gp[tb + j];
                float2 yb = gy[tb + j];
                float k12 = g.x + g.y;
                float km  = k12 + g.z;
                float Ib0 = yb.x - m0;
                float Ib1 = yb.y - m1;
                float vu0 = fmaf(g.y, Ib0, V0);
                float vu1 = fmaf(g.y, Ib1, V1);
                float mn0 = fmaf(km, Ib0, mV0);
                float mn1 = fmaf(km, Ib1, mV1);
                float Pn0 = fmaf(k12, Ib0, PV0);
                float Pn1 = fmaf(k12, Ib1, PV1);
                mV0 = mn0 + vu0;  mV1 = mn1 + vu1;
                PV0 = Pn0 + vu0;  PV1 = Pn1 + vu1;
                m0 = mn0;  m1 = mn1;
                V0 = vu0;  V1 = vu1;
                float ss = fmaf(Ib1, Ib1, Ib0 * Ib0);
                llq = fmaf(g.w, ss, llq);
            }
        }
        if (lane == 0) {
            s_pub[0] = m0; s_pub[1] = V0; s_pub[2] = PV0;
            s_pub[3] = m1; s_pub[4] = V1; s_pub[5] = PV1;
            s_pub[6] = llq;
        }
    }
    __syncthreads();

    // ------- phase 2a (no ybar dependency): gain fill + logdet -----
    {
        float4 fa = Gp[31], fb = Gp[47], fc = Gp[63];
        float ls = 0.0f;
        for (int t = tid; t < T_STEPS; t += 256) {
            float4 g;
            if (t >= T1) {
                float x  = frcp((float)(t + 1));
                float ea = x - XA, eb = x - XB, ec = x - XC;
                float L0 = eb * ec * IDA;
                float L1 = ea * ec * IDB;
                float L2 = ea * eb * IDC;
                g.x = fmaf(L0, fa.x, fmaf(L1, fb.x, L2 * fc.x));
                g.y = fmaf(L0, fa.y, fmaf(L1, fb.y, L2 * fc.y));
                g.z = fmaf(L0, fa.z, fmaf(L1, fb.z, L2 * fc.z));
                g.w = fmaf(L0, fa.w, fmaf(L1, fb.w, L2 * fc.w));
                Gp[t] = g;
            } else {
                g = Gp[t];
            }
            ls += __log2f(g.w);
        }
        #pragma unroll
        for (int m = 16; m; m >>= 1)
            ls += __shfl_xor_sync(0xffffffffu, ls, m);
        if (lane == 0) s_red[wid] = ls;          // s_red[0..7]
    }

    // ------- wait for all ybar chunks, bulk stage -------
    if (tid == 0) { while (ldacq(&g_ctrA) < NCHK) {} }
    __syncthreads();
    {
        const float4* src = (const float4*)g_ybar;
        float4*       dst = (float4*)ybp;
        #pragma unroll
        for (int i = tid; i < 2 * T_STEPS / 4; i += 256) dst[i] = src[i];
    }
    __syncthreads();

    // ---- phase 2b: per-chunk affine maps (s = (m, V, PV)) into cmpA ----
    if (tid < CH2) {
        float c11 = 1.f, c21 = 0.f, c31 = 0.f;
        float c12 = 0.f, c22 = 1.f, c32 = 0.f;
        float bx1 = 0.f, bx2 = 0.f, bx3 = 0.f;
        float by1 = 0.f, by2 = 0.f, by3 = 0.f;
        const int base = T1 + tid * WIN2;
        #pragma unroll 4
        for (int j = 0; j < WIN2; ++j) {
            float4 g  = Gp[base + j];
            float2 yb = ybp[base + j];
            float k2v = g.y;
            float k12 = g.x + g.y;
            float km  = k12 + g.z;
            float k31 = k12 + k2v;
            {
                float n1 = fmaf(-km,  c11, c11 + c21);
                float n2 = fmaf(-k2v, c11, c21);
                float n3 = fmaf(-k31, c11, c21 + c31);
                c11 = n1; c21 = n2; c31 = n3;
            }
            {
                float n1 = fmaf(-km,  c12, c12 + c22);
                float n2 = fmaf(-k2v, c12, c22);
                float n3 = fmaf(-k31, c12, c22 + c32);
                c12 = n1; c22 = n2; c32 = n3;
            }
            {
                float n1 = fmaf(km,  yb.x, fmaf(-km,  bx1, bx1 + bx2));
                float n2 = fmaf(k2v, yb.x, fmaf(-k2v, bx1, bx2));
                float n3 = fmaf(k31, yb.x, fmaf(-k31, bx1, bx2 + bx3));
                bx1 = n1; bx2 = n2; bx3 = n3;
                float p1 = fmaf(km,  yb.y, fmaf(-km,  by1, by1 + by2));
                float p2 = fmaf(k2v, yb.y, fmaf(-k2v, by1, by2));
                float p3 = fmaf(k31, yb.y, fmaf(-k31, by1, by2 + by3));
                by1 = p1; by2 = p2; by3 = p3;
            }
        }
        float* r = cmpA + tid * 12;
        r[0] = c11; r[1] = c21; r[2] = c31;
        r[3] = c12; r[4] = c22; r[5] = c32;
        r[6] = bx1; r[7] = bx2; r[8] = bx3;
        r[9] = by1; r[10] = by2; r[11] = by3;
    }
    __syncthreads();

    // ---- phase 2c: Kogge-Stone inclusive scan of affine maps ----
    // scan[k] = map_k o ... o map_0.  C = B o A (A = earlier segment).
    {
        float* src = cmpA;
        float* dst = cmpB;
        #pragma unroll
        for (int dgap = 1; dgap < 128; dgap <<= 1) {
            if (tid < CH2) {
                const float* Bp = src + tid * 12;
                float C[12];
                if (tid >= dgap) {
                    const float* Ap = src + (tid - dgap) * 12;
                    float B0 = Bp[0], B1 = Bp[1], B2 = Bp[2];
                    float B3 = Bp[3], B4 = Bp[4], B5 = Bp[5];
                    float A0 = Ap[0], A1 = Ap[1], A3 = Ap[3], A4 = Ap[4];
                    C[0] = fmaf(B0, A0, B3 * A1);
                    C[1] = fmaf(B1, A0, B4 * A1);
                    C[2] = fmaf(B2, A0, fmaf(B5, A1, Ap[2]));
                    C[3] = fmaf(B0, A3, B3 * A4);
                    C[4] = fmaf(B1, A3, B4 * A4);
                    C[5] = fmaf(B2, A3, fmaf(B5, A4, Ap[5]));
                    float A6 = Ap[6], A7 = Ap[7];
                    C[6] = fmaf(B0, A6, fmaf(B3, A7, Bp[6]));
                    C[7] = fmaf(B1, A6, fmaf(B4, A7, Bp[7]));
                    C[8] = fmaf(B2, A6, fmaf(B5, A7, Ap[8] + Bp[8]));
                    float A9 = Ap[9], A10 = Ap[10];
                    C[9]  = fmaf(B0, A9, fmaf(B3, A10, Bp[9]));
                    C[10] = fmaf(B1, A9, fmaf(B4, A10, Bp[10]));
                    C[11] = fmaf(B2, A9, fmaf(B5, A10, Ap[11] + Bp[11]));
                } else {
                    #pragma unroll
                    for (int i = 0; i < 12; ++i) C[i] = Bp[i];
                }
                float* Dp = dst + tid * 12;
                #pragma unroll
                for (int i = 0; i < 12; ++i) Dp[i] = C[i];
            }
            __syncthreads();
            float* tmp = src; src = dst; dst = tmp;
        }
        cmpA = src;   // final scan lives here
    }

    // -------- phase 2d: boundary from scan + replay for llq --------
    float llq2d = 0.0f;
    if (tid < CH2) {
        float i_m0 = s_pub[0], i_V0 = s_pub[1], i_P0 = s_pub[2];
        float i_m1 = s_pub[3], i_V1 = s_pub[4], i_P1 = s_pub[5];
        float m0, V0, PV0, m1, V1, PV1;
        if (tid == 0) {
            m0 = i_m0; V0 = i_V0; PV0 = i_P0;
            m1 = i_m1; V1 = i_V1; PV1 = i_P1;
        } else {
            const float* S = cmpA + (tid - 1) * 12;
            m0  = fmaf(S[0], i_m0, fmaf(S[3], i_V0, S[6]));
            V0  = fmaf(S[1], i_m0, fmaf(S[4], i_V0, S[7]));
            PV0 = fmaf(S[2], i_m0, fmaf(S[5], i_V0, i_P0 + S[8]));
            m1  = fmaf(S[0], i_m1, fmaf(S[3], i_V1, S[9]));
            V1  = fmaf(S[1], i_m1, fmaf(S[4], i_V1, S[10]));
            PV1 = fmaf(S[2], i_m1, fmaf(S[5], i_V1, i_P1 + S[11]));
        }
        float mV0 = m0 + V0, mV1 = m1 + V1;
        float Pn0 = 0.f, Pn1 = 0.f;
        const int base = T1 + tid * WIN2;
        #pragma unroll 4
        for (int j = 0; j < WIN2; ++j) {
            float4 g  = Gp[base + j];
            float2 yb = ybp[base + j];
            float k12 = g.x + g.y;
            float km  = k12 + g.z;
            float Ib0 = yb.x - m0;
            float Ib1 = yb.y - m1;
            float vu0 = fmaf(g.y, Ib0, V0);
            float vu1 = fmaf(g.y, Ib1, V1);
            float mn0 = fmaf(km, Ib0, mV0);
            float mn1 = fmaf(km, Ib1, mV1);
            Pn0 = fmaf(k12, Ib0, PV0);
            Pn1 = fmaf(k12, Ib1, PV1);
            mV0 = mn0 + vu0;  mV1 = mn1 + vu1;
            PV0 = Pn0 + vu0;  PV1 = Pn1 + vu1;
            m0 = mn0;  m1 = mn1;
            V0 = vu0;  V1 = vu1;
            float ss = fmaf(Ib1, Ib1, Ib0 * Ib0);
            llq2d = fmaf(g.w, ss, llq2d);
        }
        if (tid == CH2 - 1) {
            s_pub[8]  = Pn0 - V0;  s_pub[9]  = Pn1 - V1;   // posterior pos
            s_pub[10] = V0;        s_pub[11] = V1;          // posterior vel
        }
    }
    #pragma unroll
    for (int m = 16; m; m >>= 1)
        llq2d += __shfl_xor_sync(0xffffffffu, llq2d, m);
    if (lane == 0) s_red[8 + wid] = llq2d;       // s_red[8..15]

    // -------- wait sensor partials, reduce (full-MLP) --------
    if (tid == 0) { while (ldacq(&g_ctrC) < NCHK) {} }
    __syncthreads();
    {
        float accs = 0.0f;
        if (tid < OBS) {
            const float* ap = g_accp + tid;
            float a0 = 0.f, a1 = 0.f, a2 = 0.f, a3 = 0.f;
            #pragma unroll
            for (int k = 0; k < NCHK; k += 4) {
                a0 += ap[(k    ) * OBS];
                a1 += ap[(k + 1) * OBS];
                a2 += ap[(k + 2) * OBS];
                a3 += ap[(k + 3) * OBS];
            }
            accs = (a0 + a1) + (a2 + a3);
        }
        #pragma unroll
        for (int m = 16; m; m >>= 1)
            accs += __shfl_xor_sync(0xffffffffu, accs, m);
        if (lane == 0) s_red[16 + wid] = accs;   // s_red[16..23]
    }
    // reset global sync state for the next graph replay
    if (tid < NCHK) g_flagY[tid] = 0;
    if (tid == 200) g_ctrA = 0;
    if (tid == 201) g_ctrB = 0;
    if (tid == 202) g_ctrC = 0;
    __syncthreads();

    if (tid == 0) {
        float lsum = 0.f, llq = s_pub[6], atot = 0.f;
        #pragma unroll
        for (int i = 0; i < 8; ++i) {
            lsum += s_red[i];
            llq  += s_red[8 + i];
            atot += s_red[16 + i];
        }
        // covariance at T via Lagrange extrapolation to x = 1/4096
        float x  = 1.0f / 4096.0f;
        float ea = x - XA, eb = x - XB, ec = x - XC;
        float L0 = eb * ec * IDA;
        float L1 = ea * ec * IDB;
        float L2 = ea * eb * IDC;
        float a = fmaf(L0, s_fit[0], fmaf(L1, s_fit[3], L2 * s_fit[6]));
        float d = fmaf(L0, s_fit[1], fmaf(L1, s_fit[4], L2 * s_fit[7]));
        float c = fmaf(L0, s_fit[2], fmaf(L1, s_fit[5], L2 * s_fit[8]));

        double ldS = -(double)lsum;
        double ldA = (double)(T_STEPS - 1) * log2((double)R)
                   + log2((double)R + (double)T_STEPS * (double)g0);
        double ld  = 63.0 * ldA + ldS + 6.0 * (double)T_STEPS;
        const double LN2    = 0.6931471805599453094;
        const double LOG2PI = 1.8378770664093454836;
        double quad = 0.5 * ((double)atot + (double)llq);
        double logp = -quad - ld * LN2 - 64.0 * (double)T_STEPS * LOG2PI;
        out[0] = (float)logp;
        out[1] = s_pub[8];  out[2] = s_pub[9];
        out[3] = s_pub[10]; out[4] = s_pub[11];
        out[5]  = a;   out[6]  = 0.f; out[7]  = d;   out[8]  = 0.f;
        out[9]  = 0.f; out[10] = a;   out[11] = 0.f; out[12] = d;
        out[13] = d;   out[14] = 0.f; out[15] = c;   out[16] = 0.f;
        out[17] = 0.f; out[18] = d;   out[19] = 0.f; out[20] = c;
    }
}

extern "C" void kernel_launch(void* const* d_in, const int* in_sizes, int n_in,
                              void* d_out, int out_size) {
    const float* obs = (const float*)d_in[0];
    const float* lbs = (const float*)d_in[1];
    const float* lon = (const float*)d_in[2];
    const float* ltn = (const float*)d_in[3];
    float* out = (float*)d_out;
    (void)in_sizes; (void)n_in; (void)out_size;

    static bool attr_set = false;
    if (!attr_set) {
        cudaFuncSetAttribute(fused_kernel,
                             cudaFuncAttributeMaxDynamicSharedMemorySize,
                             SMEM_BYTES);
        attr_set = true;
    }
    fused_kernel<<<NCHK + 1, 256, SMEM_BYTES>>>(
        (const float4*)obs, lbs, lon, ltn, out);
}

// round 14
// speedup vs baseline: 1.3596x; 1.0622x over previous
#include <cuda_runtime.h>

// Kalman: NCV(4) + 128 static sensor biases, T=4096.
// Round 14: T1=32 (nodes tau=16/24/32), WIN2=16 (254-chunk scan),
// ybar staged by warps 2-7 DURING phase 1 (named barrier 2).
// Workers unchanged (validated rounds 12-13).

#define T_STEPS 4096
#define OBS 128
#define T1 32
#define WIN1 8
#define NW1 (T1 / WIN1)               // 4
#define WIN2 16
#define CH2 ((T_STEPS - T1) / WIN2)   // 254
#define NCHK 64                        // worker chunks (64 steps each)

__device__ float g_ybar[2 * T_STEPS];
__device__ float g_csum[NCHK * OBS];
__device__ float g_accp[NCHK * OBS];
__device__ int   g_flagY[NCHK];
__device__ int   g_ctrA, g_ctrB, g_ctrC;

__device__ __forceinline__ float frcp(float x) {
    float r;
    asm("rcp.approx.f32 %0, %1;" : "=f"(r) : "f"(x));
    return r;
}
__device__ __forceinline__ int ldacq(const int* p) {
    int v;
    asm volatile("ld.acquire.gpu.s32 %0, [%1];" : "=r"(v) : "l"(p) : "memory");
    return v;
}
__device__ __forceinline__ void strel(int* p, int v) {
    asm volatile("st.release.gpu.s32 [%0], %1;" :: "l"(p), "r"(v) : "memory");
}

// ---- master smem layout (float offsets) ----
#define OFF_G    0            // float4[4096]  -> 16384
#define OFF_YB   16384        // float2[4096]  ->  8192
#define OFF_CMPA 24576        // 254*12 = 3048
#define OFF_CMPB 27624        // 254*12 = 3048
#define OFF_RED  30672        // 32
#define OFF_FIT  30704        // 16
#define OFF_PUB  30720        // 16
#define SMEM_FLOATS 30736
#define SMEM_BYTES  (SMEM_FLOATS * 4)

// Lagrange nodes x = 1/tau at tau = 16, 24, 32  (x->0 weights: 2, -9, 8)
#define XA (1.0f / 16.0f)
#define XB (1.0f / 24.0f)
#define XC (1.0f / 32.0f)
#define IDA (  1536.0f)
#define IDB ( -4608.0f)
#define IDC (  3072.0f)

__global__ void __launch_bounds__(256, 1) fused_kernel(
    const float4* __restrict__ obs4,
    const float* __restrict__ lbs,
    const float* __restrict__ lon,
    const float* __restrict__ ltn,
    float* __restrict__ out)
{
    extern __shared__ float smem[];
    const int tid  = threadIdx.x;
    const int bid  = blockIdx.x;
    const int wid  = tid >> 5;
    const int lane = tid & 31;

    const float R  = expf(2.0f * lon[0]);
    const float q  = expf(2.0f * ltn[0]);
    const float g0 = expf(2.0f * lbs[0]);

    if (bid < NCHK) {
        // ==================== WORKER block: chunk bid ====================
        float* tile = smem;            // [64][128] floats (32 KB)
        float* yloc = smem + 8192;     // [2*64]
        float* itg  = smem + 8320;     // [64]
        float* iaT  = smem + 8384;     // [64]
        const int c  = bid;
        const int c0 = c * 64;

        // step 1a: batch all 8 global loads (full MLP)
        float4 v[8];
        #pragma unroll
        for (int k = 0; k < 8; ++k)
            v[k] = obs4[(c0 + wid * 8 + k) * 32 + lane];

        // step 1b: store tile + ybar reductions
        #pragma unroll
        for (int k = 0; k < 8; ++k) {
            int tl = wid * 8 + k;
            int t  = c0 + tl;
            ((float4*)tile)[tl * 32 + lane] = v[k];
            float s = (v[k].x + v[k].y) + (v[k].z + v[k].w);
            #pragma unroll
            for (int m = 8; m; m >>= 1)
                s += __shfl_xor_sync(0xffffffffu, s, m);
            s *= 0.015625f;
            if (lane == 0)  { yloc[2 * tl]     = s; g_ybar[2 * t]     = s; }
            if (lane == 16) { yloc[2 * tl + 1] = s; g_ybar[2 * t + 1] = s; }
        }
        if (tid < 64) {
            int t = c0 + tid;
            float den0 = fmaf((float)t, g0, R);
            float den1 = den0 + g0;
            itg[tid] = g0 * frcp(den0);
            iaT[tid] = den0 * frcp(den1) * frcp(R);
        }
        __syncthreads();
        if (tid == 0) {
            strel(&g_flagY[c], 1);
            __threadfence();
            atomicAdd(&g_ctrA, 1);
        }

        // step 2: per-sensor chunk sums
        if (tid < OBS) {
            const int comp = tid >> 6;
            float cs = 0.0f;
            #pragma unroll 8
            for (int i = 0; i < 64; ++i)
                cs += tile[i * OBS + tid] - yloc[2 * i + comp];
            g_csum[c * OBS + tid] = cs;
        }
        __syncthreads();
        if (tid == 0) {
            __threadfence();
            atomicAdd(&g_ctrB, 1);
            while (ldacq(&g_ctrB) < NCHK) {}
        }
        __syncthreads();

        // step 3: exclusive prefix (full-MLP, predicated) + replay partial
        if (tid < OBS) {
            const float* cp = g_csum + tid;
            float p0 = 0.f, p1 = 0.f, p2 = 0.f, p3 = 0.f;
            #pragma unroll
            for (int k = 0; k < NCHK; k += 4) {
                if (k     < c) p0 += cp[(k    ) * OBS];
                if (k + 1 < c) p1 += cp[(k + 1) * OBS];
                if (k + 2 < c) p2 += cp[(k + 2) * OBS];
                if (k + 3 < c) p3 += cp[(k + 3) * OBS];
            }
            float S = (p0 + p1) + (p2 + p3);
            const int comp = tid >> 6;
            float acc = 0.0f;
            #pragma unroll 8
            for (int i = 0; i < 64; ++i) {
                float x  = tile[i * OBS + tid] - yloc[2 * i + comp];
                float rt = fmaf(-S, itg[i], x);
                S += x;
                acc = fmaf(iaT[i], rt * rt, acc);
            }
            g_accp[c * OBS + tid] = acc;
        }
        __syncthreads();
        if (tid == 0) { __threadfence(); atomicAdd(&g_ctrC, 1); }
        return;
    }

    // ======================= MASTER block =======================
    float4* Gp    = (float4*)(smem + OFF_G);
    float2* ybp   = (float2*)(smem + OFF_YB);
    float*  cmpA  = smem + OFF_CMPA;
    float*  cmpB  = smem + OFF_CMPB;
    float*  s_red = smem + OFF_RED;
    float*  s_fit = smem + OFF_FIT;
    float*  s_pub = smem + OFF_PUB;

    const float q1 = q, q2 = 0.5f * q, q3 = q * (1.0f / 3.0f);
    const float R64 = R * 0.015625f;

    if (wid == 0) {
        // ------- Riccati chain, t < T1 (starts immediately) ----
        float a = 100.0f, c = 100.0f, d = 0.0f;
        float E = 0.0f, F = 0.0f, G = g0 * 0.015625f;
        float is = 1.0f;
        const bool st = (lane == 0);
        for (int w = 0; w < NW1; ++w) {
            const bool exact = (w == 0);
            #pragma unroll 8
            for (int j = 0; j < WIN1; ++j) {
                float cp = c + q1;
                float dp = (d + c) + q2;
                float ap = fmaf(2.0f, d, a) + (c + q3);
                float Ep = E + F;
                float u1 = ap + Ep;
                float u2 = dp + F;
                float u3 = Ep + G;
                float Sv = (u1 + u3) + R64;
                if (exact) is = frcp(Sv);
                else       is = is * fmaf(-Sv, is, 2.0f);
                float k1 = u1 * is, k2 = u2 * is, k3 = u3 * is;
                a = fmaf(-k1, u1, ap);
                d = fmaf(-k1, u2, dp);
                c = fmaf(-k2, u2, cp);
                E = fmaf(-k1, u3, Ep);
                F = fmaf(-k2, u3, F);
                G = fmaf(-k3, u3, G);
                if (st) Gp[w * WIN1 + j] = make_float4(k1, k2, k3, is);
            }
            if (st) {
                if (w == 1) { s_fit[0] = a; s_fit[1] = d; s_fit[2] = c; } // tau=16
                if (w == 2) { s_fit[3] = a; s_fit[4] = d; s_fit[5] = c; } // tau=24
                if (w == 3) { s_fit[6] = a; s_fit[7] = d; s_fit[8] = c; } // tau=32
            }
            asm volatile("bar.sync 1, 64;" ::: "memory");
        }
    } else if (wid == 1) {
        // --- mean / loglik chain t < T1 (ybar in worker chunk 0) ---
        const float2* gy = (const float2*)g_ybar;
        float m0 = 0.f, m1 = 0.f, V0 = 0.f, V1 = 0.f;
        float mV0 = 0.f, mV1 = 0.f, PV0 = 0.f, PV1 = 0.f;
        float llq = 0.f;
        for (int w = 0; w < NW1; ++w) {
            if (w == 0) { while (ldacq(&g_flagY[0]) == 0) {} }
            asm volatile("bar.sync 1, 64;" ::: "memory");
            const int tb = w * WIN1;
            #pragma unroll 8
            for (int j = 0; j < WIN1; ++j) {
                float4 g  = Gp[tb + j];
                float2 yb = gy[tb + j];
                float k12 = g.x + g.y;
                float km  = k12 + g.z;
                float Ib0 = yb.x - m0;
                float Ib1 = yb.y - m1;
                float vu0 = fmaf(g.y, Ib0, V0);
                float vu1 = fmaf(g.y, Ib1, V1);
                float mn0 = fmaf(km, Ib0, mV0);
                float mn1 = fmaf(km, Ib1, mV1);
                float Pn0 = fmaf(k12, Ib0, PV0);
                float Pn1 = fmaf(k12, Ib1, PV1);
                mV0 = mn0 + vu0;  mV1 = mn1 + vu1;
                PV0 = Pn0 + vu0;  PV1 = Pn1 + vu1;
                m0 = mn0;  m1 = mn1;
                V0 = vu0;  V1 = vu1;
                float ss = fmaf(Ib1, Ib1, Ib0 * Ib0);
                llq = fmaf(g.w, ss, llq);
            }
        }
        if (lane == 0) {
            s_pub[0] = m0; s_pub[1] = V0; s_pub[2] = PV0;
            s_pub[3] = m1; s_pub[4] = V1; s_pub[5] = PV1;
            s_pub[6] = llq;
        }
    } else {
        // ---- warps 2-7: stage ybar into smem DURING phase 1 ----
        if (tid == 64) { while (ldacq(&g_ctrA) < NCHK) {} }
        asm volatile("bar.sync 2, 192;" ::: "memory");
        const float4* src = (const float4*)g_ybar;
        float4*       dst = (float4*)ybp;
        for (int i = tid - 64; i < 2 * T_STEPS / 4; i += 192)
            dst[i] = src[i];
    }
    __syncthreads();

    // ------- phase 2a: gain fill (Lagrange in 1/tau) + logdet -----
    {
        float4 fa = Gp[15], fb = Gp[23], fc = Gp[31];
        float ls = 0.0f;
        for (int t = tid; t < T_STEPS; t += 256) {
            float4 g;
            if (t >= T1) {
                float x  = frcp((float)(t + 1));
                float ea = x - XA, eb = x - XB, ec = x - XC;
                float L0 = eb * ec * IDA;
                float L1 = ea * ec * IDB;
                float L2 = ea * eb * IDC;
                g.x = fmaf(L0, fa.x, fmaf(L1, fb.x, L2 * fc.x));
                g.y = fmaf(L0, fa.y, fmaf(L1, fb.y, L2 * fc.y));
                g.z = fmaf(L0, fa.z, fmaf(L1, fb.z, L2 * fc.z));
                g.w = fmaf(L0, fa.w, fmaf(L1, fb.w, L2 * fc.w));
                Gp[t] = g;
            } else {
                g = Gp[t];
            }
            ls += __log2f(g.w);
        }
        #pragma unroll
        for (int m = 16; m; m >>= 1)
            ls += __shfl_xor_sync(0xffffffffu, ls, m);
        if (lane == 0) s_red[wid] = ls;          // s_red[0..7]
    }
    __syncthreads();

    // ---- phase 2b: per-chunk affine maps (s = (m, V, PV)) into cmpA ----
    if (tid < CH2) {
        float c11 = 1.f, c21 = 0.f, c31 = 0.f;
        float c12 = 0.f, c22 = 1.f, c32 = 0.f;
        float bx1 = 0.f, bx2 = 0.f, bx3 = 0.f;
        float by1 = 0.f, by2 = 0.f, by3 = 0.f;
        const int base = T1 + tid * WIN2;
        #pragma unroll 4
        for (int j = 0; j < WIN2; ++j) {
            float4 g  = Gp[base + j];
            float2 yb = ybp[base + j];
            float k2v = g.y;
            float k12 = g.x + g.y;
            float km  = k12 + g.z;
            float k31 = k12 + k2v;
            {
                float n1 = fmaf(-km,  c11, c11 + c21);
                float n2 = fmaf(-k2v, c11, c21);
                float n3 = fmaf(-k31, c11, c21 + c31);
                c11 = n1; c21 = n2; c31 = n3;
            }
            {
                float n1 = fmaf(-km,  c12, c12 + c22);
                float n2 = fmaf(-k2v, c12, c22);
                float n3 = fmaf(-k31, c12, c22 + c32);
                c12 = n1; c22 = n2; c32 = n3;
            }
            {
                float n1 = fmaf(km,  yb.x, fmaf(-km,  bx1, bx1 + bx2));
                float n2 = fmaf(k2v, yb.x, fmaf(-k2v, bx1, bx2));
                float n3 = fmaf(k31, yb.x, fmaf(-k31, bx1, bx2 + bx3));
                bx1 = n1; bx2 = n2; bx3 = n3;
                float p1 = fmaf(km,  yb.y, fmaf(-km,  by1, by1 + by2));
                float p2 = fmaf(k2v, yb.y, fmaf(-k2v, by1, by2));
                float p3 = fmaf(k31, yb.y, fmaf(-k31, by1, by2 + by3));
                by1 = p1; by2 = p2; by3 = p3;
            }
        }
        float* r = cmpA + tid * 12;
        r[0] = c11; r[1] = c21; r[2] = c31;
        r[3] = c12; r[4] = c22; r[5] = c32;
        r[6] = bx1; r[7] = bx2; r[8] = bx3;
        r[9] = by1; r[10] = by2; r[11] = by3;
    }
    __syncthreads();

    // ---- phase 2c: Kogge-Stone inclusive scan of affine maps ----
    {
        float* src = cmpA;
        float* dst = cmpB;
        #pragma unroll
        for (int dgap = 1; dgap < 256; dgap <<= 1) {
            if (tid < CH2) {
                const float* Bp = src + tid * 12;
                float C[12];
                if (tid >= dgap) {
                    const float* Ap = src + (tid - dgap) * 12;
                    float B0 = Bp[0], B1 = Bp[1], B2 = Bp[2];
                    float B3 = Bp[3], B4 = Bp[4], B5 = Bp[5];
                    float A0 = Ap[0], A1 = Ap[1], A3 = Ap[3], A4 = Ap[4];
                    C[0] = fmaf(B0, A0, B3 * A1);
                    C[1] = fmaf(B1, A0, B4 * A1);
                    C[2] = fmaf(B2, A0, fmaf(B5, A1, Ap[2]));
                    C[3] = fmaf(B0, A3, B3 * A4);
                    C[4] = fmaf(B1, A3, B4 * A4);
                    C[5] = fmaf(B2, A3, fmaf(B5, A4, Ap[5]));
                    float A6 = Ap[6], A7 = Ap[7];
                    C[6] = fmaf(B0, A6, fmaf(B3, A7, Bp[6]));
                    C[7] = fmaf(B1, A6, fmaf(B4, A7, Bp[7]));
                    C[8] = fmaf(B2, A6, fmaf(B5, A7, Ap[8] + Bp[8]));
                    float A9 = Ap[9], A10 = Ap[10];
                    C[9]  = fmaf(B0, A9, fmaf(B3, A10, Bp[9]));
                    C[10] = fmaf(B1, A9, fmaf(B4, A10, Bp[10]));
                    C[11] = fmaf(B2, A9, fmaf(B5, A10, Ap[11] + Bp[11]));
                } else {
                    #pragma unroll
                    for (int i = 0; i < 12; ++i) C[i] = Bp[i];
                }
                float* Dp = dst + tid * 12;
                #pragma unroll
                for (int i = 0; i < 12; ++i) Dp[i] = C[i];
            }
            __syncthreads();
            float* tmp = src; src = dst; dst = tmp;
        }
        cmpA = src;   // final scan lives here
    }

    // -------- phase 2d: boundary from scan + replay for llq --------
    float llq2d = 0.0f;
    if (tid < CH2) {
        float i_m0 = s_pub[0], i_V0 = s_pub[1], i_P0 = s_pub[2];
        float i_m1 = s_pub[3], i_V1 = s_pub[4], i_P1 = s_pub[5];
        float m0, V0, PV0, m1, V1, PV1;
        if (tid == 0) {
            m0 = i_m0; V0 = i_V0; PV0 = i_P0;
            m1 = i_m1; V1 = i_V1; PV1 = i_P1;
        } else {
            const float* S = cmpA + (tid - 1) * 12;
            m0  = fmaf(S[0], i_m0, fmaf(S[3], i_V0, S[6]));
            V0  = fmaf(S[1], i_m0, fmaf(S[4], i_V0, S[7]));
            PV0 = fmaf(S[2], i_m0, fmaf(S[5], i_V0, i_P0 + S[8]));
            m1  = fmaf(S[0], i_m1, fmaf(S[3], i_V1, S[9]));
            V1  = fmaf(S[1], i_m1, fmaf(S[4], i_V1, S[10]));
            PV1 = fmaf(S[2], i_m1, fmaf(S[5], i_V1, i_P1 + S[11]));
        }
        float mV0 = m0 + V0, mV1 = m1 + V1;
        float Pn0 = 0.f, Pn1 = 0.f;
        const int base = T1 + tid * WIN2;
        #pragma unroll 4
        for (int j = 0; j < WIN2; ++j) {
            float4 g  = Gp[base + j];
            float2 yb = ybp[base + j];
            float k12 = g.x + g.y;
            float km  = k12 + g.z;
            float Ib0 = yb.x - m0;
            float Ib1 = yb.y - m1;
            float vu0 = fmaf(g.y, Ib0, V0);
            float vu1 = fmaf(g.y, Ib1, V1);
            float mn0 = fmaf(km, Ib0, mV0);
            float mn1 = fmaf(km, Ib1, mV1);
            Pn0 = fmaf(k12, Ib0, PV0);
            Pn1 = fmaf(k12, Ib1, PV1);
            mV0 = mn0 + vu0;  mV1 = mn1 + vu1;
            PV0 = Pn0 + vu0;  PV1 = Pn1 + vu1;
            m0 = mn0;  m1 = mn1;
            V0 = vu0;  V1 = vu1;
            float ss = fmaf(Ib1, Ib1, Ib0 * Ib0);
            llq2d = fmaf(g.w, ss, llq2d);
        }
        if (tid == CH2 - 1) {
            s_pub[8]  = Pn0 - V0;  s_pub[9]  = Pn1 - V1;   // posterior pos
            s_pub[10] = V0;        s_pub[11] = V1;          // posterior vel
        }
    }
    #pragma unroll
    for (int m = 16; m; m >>= 1)
        llq2d += __shfl_xor_sync(0xffffffffu, llq2d, m);
    if (lane == 0) s_red[8 + wid] = llq2d;       // s_red[8..15]

    // -------- wait sensor partials, reduce (full-MLP) --------
    if (tid == 0) { while (ldacq(&g_ctrC) < NCHK) {} }
    __syncthreads();
    {
        float accs = 0.0f;
        if (tid < OBS) {
            const float* ap = g_accp + tid;
            float a0 = 0.f, a1 = 0.f, a2 = 0.f, a3 = 0.f;
            #pragma unroll
            for (int k = 0; k < NCHK; k += 4) {
                a0 += ap[(k    ) * OBS];
                a1 += ap[(k + 1) * OBS];
                a2 += ap[(k + 2) * OBS];
                a3 += ap[(k + 3) * OBS];
            }
            accs = (a0 + a1) + (a2 + a3);
        }
        #pragma unroll
        for (int m = 16; m; m >>= 1)
            accs += __shfl_xor_sync(0xffffffffu, accs, m);
        if (lane == 0) s_red[16 + wid] = accs;   // s_red[16..23]
    }
    // reset global sync state for the next graph replay
    if (tid < NCHK) g_flagY[tid] = 0;
    if (tid == 200) g_ctrA = 0;
    if (tid == 201) g_ctrB = 0;
    if (tid == 202) g_ctrC = 0;
    __syncthreads();

    if (tid == 0) {
        float lsum = 0.f, llq = s_pub[6], atot = 0.f;
        #pragma unroll
        for (int i = 0; i < 8; ++i) {
            lsum += s_red[i];
            llq  += s_red[8 + i];
            atot += s_red[16 + i];
        }
        // covariance at T via Lagrange extrapolation to x = 1/4096
        float x  = 1.0f / 4096.0f;
        float ea = x - XA, eb = x - XB, ec = x - XC;
        float L0 = eb * ec * IDA;
        float L1 = ea * ec * IDB;
        float L2 = ea * eb * IDC;
        float a = fmaf(L0, s_fit[0], fmaf(L1, s_fit[3], L2 * s_fit[6]));
        float d = fmaf(L0, s_fit[1], fmaf(L1, s_fit[4], L2 * s_fit[7]));
        float c = fmaf(L0, s_fit[2], fmaf(L1, s_fit[5], L2 * s_fit[8]));

        double ldS = -(double)lsum;
        double ldA = (double)(T_STEPS - 1) * log2((double)R)
                   + log2((double)R + (double)T_STEPS * (double)g0);
        double ld  = 63.0 * ldA + ldS + 6.0 * (double)T_STEPS;
        const double LN2    = 0.6931471805599453094;
        const double LOG2PI = 1.8378770664093454836;
        double quad = 0.5 * ((double)atot + (double)llq);
        double logp = -quad - ld * LN2 - 64.0 * (double)T_STEPS * LOG2PI;
        out[0] = (float)logp;
        out[1] = s_pub[8];  out[2] = s_pub[9];
        out[3] = s_pub[10]; out[4] = s_pub[11];
        out[5]  = a;   out[6]  = 0.f; out[7]  = d;   out[8]  = 0.f;
        out[9]  = 0.f; out[10] = a;   out[11] = 0.f; out[12] = d;
        out[13] = d;   out[14] = 0.f; out[15] = c;   out[16] = 0.f;
        out[17] = 0.f; out[18] = d;   out[19] = 0.f; out[20] = c;
    }
}

extern "C" void kernel_launch(void* const* d_in, const int* in_sizes, int n_in,
                              void* d_out, int out_size) {
    const float* obs = (const float*)d_in[0];
    const float* lbs = (const float*)d_in[1];
    const float* lon = (const float*)d_in[2];
    const float* ltn = (const float*)d_in[3];
    float* out = (float*)d_out;
    (void)in_sizes; (void)n_in; (void)out_size;

    static bool attr_set = false;
    if (!attr_set) {
        cudaFuncSetAttribute(fused_kernel,
                             cudaFuncAttributeMaxDynamicSharedMemorySize,
                             SMEM_BYTES);
        attr_set = true;
    }
    fused_kernel<<<NCHK + 1, 256, SMEM_BYTES>>>(
        (const float4*)obs, lbs, lon, ltn, out);
}